// round 2
// baseline (speedup 1.0000x reference)
#include <cuda_runtime.h>
#include <cstdint>

// EntailmentConeLoss: loss = 0.5 * ( mean_i E(p_i, cpos_i) + mean_{i,k} relu(MARGIN - E(p_i, cneg_{i,k})) )
// E(p,c) = relu(acos(clip((|c|^2-|p|^2-|c-p|^2)/(2|p||c-p|+eps))) - asin(clip(BETA/(|p|+eps),0,1-eps)))

#define C_CONST 100000
#define D_CONST 256
#define P_CONST 65536
#define K_CONST 4
#define BETA 0.1f
#define MARGIN 0.1f
#define EPS 1e-6f

#define WARPS_PER_BLOCK 8
#define THREADS_PER_BLOCK (WARPS_PER_BLOCK * 32)
#define NUM_BLOCKS (P_CONST / WARPS_PER_BLOCK)   // 8192

__device__ float g_partials[NUM_BLOCKS];

__device__ __forceinline__ float warp_sum(float v) {
    #pragma unroll
    for (int o = 16; o > 0; o >>= 1) v += __shfl_xor_sync(0xFFFFFFFFu, v, o);
    return v;
}

// Clip to reference: cos in [-1+eps, 1-eps]; sin-arg in [0, 1-eps]
__device__ __forceinline__ float energy_from_sums(float sp2, float sc2, float sd2, float norm_p) {
    float num   = sc2 - sp2 - sd2;
    float denom = 2.0f * norm_p * sqrtf(sd2) + EPS;
    float cosang = num / denom;
    cosang = fminf(fmaxf(cosang, -1.0f + EPS), 1.0f - EPS);
    float ang = acosf(cosang);
    float sa  = BETA / (norm_p + EPS);
    sa = fminf(fmaxf(sa, 0.0f), 1.0f - EPS);
    float aperture = asinf(sa);
    return fmaxf(ang - aperture, 0.0f);
}

__global__ __launch_bounds__(THREADS_PER_BLOCK)
void cone_loss_kernel(const float* __restrict__ protos,
                      const int*   __restrict__ pairs,
                      const int*   __restrict__ neg_c) {
    const int wid  = threadIdx.x >> 5;
    const int lane = threadIdx.x & 31;
    const int pair = blockIdx.x * WARPS_PER_BLOCK + wid;   // one warp per pair

    __shared__ float s_warp[WARPS_PER_BLOCK];

    // ---- load p (1 row, 256 floats) into registers: 2x float4 per lane ----
    const int p_idx = pairs[2 * pair + 0];
    const int c_idx = pairs[2 * pair + 1];
    const float4* prow = reinterpret_cast<const float4*>(protos) + (size_t)p_idx * (D_CONST / 4);
    float4 pa = __ldg(&prow[lane]);
    float4 pb = __ldg(&prow[lane + 32]);

    float sp2_part = pa.x*pa.x + pa.y*pa.y + pa.z*pa.z + pa.w*pa.w
                   + pb.x*pb.x + pb.y*pb.y + pb.z*pb.z + pb.w*pb.w;
    float sp2 = warp_sum(sp2_part);
    float norm_p = sqrtf(sp2);

    // ---- helper lambda-ish: process one c row ----
    auto process_c = [&](int cidx) -> float {
        const float4* crow = reinterpret_cast<const float4*>(protos) + (size_t)cidx * (D_CONST / 4);
        float4 ca = __ldg(&crow[lane]);
        float4 cb = __ldg(&crow[lane + 32]);
        float sc2_part = ca.x*ca.x + ca.y*ca.y + ca.z*ca.z + ca.w*ca.w
                       + cb.x*cb.x + cb.y*cb.y + cb.z*cb.z + cb.w*cb.w;
        float dax = ca.x - pa.x, day = ca.y - pa.y, daz = ca.z - pa.z, daw = ca.w - pa.w;
        float dbx = cb.x - pb.x, dby = cb.y - pb.y, dbz = cb.z - pb.z, dbw = cb.w - pb.w;
        float sd2_part = dax*dax + day*day + daz*daz + daw*daw
                       + dbx*dbx + dby*dby + dbz*dbz + dbw*dbw;
        // pack both sums into one pair of reductions
        float sc2 = warp_sum(sc2_part);
        float sd2 = warp_sum(sd2_part);
        return energy_from_sums(sp2, sc2, sd2, norm_p);
    };

    float e_pos = process_c(c_idx);

    float neg_sum = 0.0f;
    #pragma unroll
    for (int k = 0; k < K_CONST; k++) {
        int nc = neg_c[pair * K_CONST + k];
        float e = process_c(nc);
        neg_sum += fmaxf(MARGIN - e, 0.0f);
    }

    // per-pair contribution to final scalar
    if (lane == 0) {
        float contrib = 0.5f * (e_pos * (1.0f / (float)P_CONST)
                              + neg_sum * (1.0f / ((float)P_CONST * (float)K_CONST)));
        s_warp[wid] = contrib;
    }
    __syncthreads();

    if (threadIdx.x == 0) {
        float acc = 0.0f;
        #pragma unroll
        for (int w = 0; w < WARPS_PER_BLOCK; w++) acc += s_warp[w];
        g_partials[blockIdx.x] = acc;
    }
}

__global__ __launch_bounds__(256)
void reduce_kernel(float* __restrict__ out) {
    __shared__ float s[256];
    float acc = 0.0f;
    // NUM_BLOCKS = 8192 = 256 * 32
    for (int j = threadIdx.x; j < NUM_BLOCKS; j += 256) acc += g_partials[j];
    s[threadIdx.x] = acc;
    __syncthreads();
    #pragma unroll
    for (int stride = 128; stride > 0; stride >>= 1) {
        if (threadIdx.x < stride) s[threadIdx.x] += s[threadIdx.x + stride];
        __syncthreads();
    }
    if (threadIdx.x == 0) out[0] = s[0];
}

extern "C" void kernel_launch(void* const* d_in, const int* in_sizes, int n_in,
                              void* d_out, int out_size) {
    const float* protos = (const float*)d_in[0];
    const int*   pairs  = (const int*)d_in[1];
    const int*   negc   = (const int*)d_in[2];
    float* out = (float*)d_out;

    cone_loss_kernel<<<NUM_BLOCKS, THREADS_PER_BLOCK>>>(protos, pairs, negc);
    reduce_kernel<<<1, 256>>>(out);
}